// round 15
// baseline (speedup 1.0000x reference)
#include <cuda_runtime.h>
#include <cuda_bf16.h>

// Sampler: out[row] = argmax over vocab of
//   greedy (t<=0):  logits[row, :]
//   sampled (t>0):  softmax(logits/t) / max(noise, 1e-10)
// Monotone per-element key: sampled: l - t*log(max(n,1e-10)); greedy: l.
// OUTPUT: float32 index (confirmed in R12; exact below 2^24).
//
// Single fused kernel: each (row, part) block reduces its slice, atomicMax's an
// order-preserving 64-bit (key, V-idx) code into a per-row slot; the LAST block
// of each row (per-row counter) decodes, writes out[row], and resets scratch to
// zero so the kernel is deterministic under CUDA-graph replay.
//
// Input identification WITHOUT metadata assumptions:
//   host:   temps = smallest array; the two largest are {logits, noise}
//   device: noise is Exp(1) (>= 0); logits ~ N(0,1) has negatives
//           -> sign-ballot over first 64 elements (P(err) = 2^-64).

#define NOISE_MIN 1e-10f
#define NT 256
#define SPLIT 4
#define MAX_ROWS 4096

__device__ unsigned long long g_slot[MAX_ROWS];  // zero-init; reset by last block
__device__ unsigned int       g_cnt[MAX_ROWS];   // zero-init; reset by last block

__device__ __forceinline__ float neg_inf() { return __int_as_float(0xff800000u); }

// order-preserving float -> uint32 (monotone increasing)
__device__ __forceinline__ unsigned int ordkey(float f) {
    unsigned int u = __float_as_uint(f);
    return (u & 0x80000000u) ? ~u : (u | 0x80000000u);
}

__device__ __forceinline__ void take_better(float& k1, int& i1, float k2, int i2) {
    if (k2 > k1 || (k2 == k1 && i2 < i1)) { k1 = k2; i1 = i2; }
}

__global__ void __launch_bounds__(NT) sampler_fused_kernel(
    const float* __restrict__ candA,   // one of {logits, noise}
    const float* __restrict__ candB,   // the other
    const float* __restrict__ temps,
    float* __restrict__ out,
    int V, int vpart, int split)
{
    const int row  = blockIdx.x / split;
    const int part = blockIdx.x % split;
    const int tid  = threadIdx.x;
    const int lane = tid & 31;

    // ---- identify logits vs noise: sign of first 64 elements of candA ----
    __shared__ int s_a_is_logits;
    if (tid < 32) {
        float p0 = __ldg(candA + lane);
        float p1 = __ldg(candA + 32 + lane);
        unsigned m = __ballot_sync(0xffffffffu, (p0 < 0.0f) || (p1 < 0.0f));
        if (lane == 0) s_a_is_logits = (m != 0u);  // Exp(1) noise never negative
    }
    __syncthreads();
    const bool a_is_logits = (s_a_is_logits != 0);
    const float* __restrict__ logits = a_is_logits ? candA : candB;
    const float* __restrict__ noise  = a_is_logits ? candB : candA;

    const float t = __ldg(temps + row);
    const bool greedy = (t <= 0.0f);

    const int start = part * vpart;
    const int len   = (start < V) ? min(vpart, V - start) : 0;
    const size_t base = (size_t)row * (size_t)V + (size_t)start;

    float k0 = neg_inf(), k1 = neg_inf(), k2 = neg_inf(), k3 = neg_inf();
    int   i0 = 0, i1 = 0, i2 = 0, i3 = 0;

    const bool vec_ok = ((V & 3) == 0) && ((vpart & 3) == 0);
    const int nvec = vec_ok ? (len >> 2) : 0;

    if (vec_ok) {
        const float4* __restrict__ lg = reinterpret_cast<const float4*>(logits + base);
        const float4* __restrict__ nz = reinterpret_cast<const float4*>(noise  + base);
        if (greedy) {
            #pragma unroll 8
            for (int i = tid; i < nvec; i += NT) {
                float4 v = lg[i];
                int b = i << 2;
                if (v.x > k0) { k0 = v.x; i0 = b;     }
                if (v.y > k1) { k1 = v.y; i1 = b + 1; }
                if (v.z > k2) { k2 = v.z; i2 = b + 2; }
                if (v.w > k3) { k3 = v.w; i3 = b + 3; }
            }
        } else {
            #pragma unroll 4
            for (int i = tid; i < nvec; i += NT) {
                float4 v = lg[i];
                float4 w = nz[i];
                int b = i << 2;
                // key = l - t * log(max(n, NOISE_MIN))  (well-conditioned for all t > 0)
                float c0 = fmaf(-t, __logf(fmaxf(w.x, NOISE_MIN)), v.x);
                float c1 = fmaf(-t, __logf(fmaxf(w.y, NOISE_MIN)), v.y);
                float c2 = fmaf(-t, __logf(fmaxf(w.z, NOISE_MIN)), v.z);
                float c3 = fmaf(-t, __logf(fmaxf(w.w, NOISE_MIN)), v.w);
                if (c0 > k0) { k0 = c0; i0 = b;     }
                if (c1 > k1) { k1 = c1; i1 = b + 1; }
                if (c2 > k2) { k2 = c2; i2 = b + 2; }
                if (c3 > k3) { k3 = c3; i3 = b + 3; }
            }
        }
    }

    // scalar path / tail (no-op when vec path covers everything)
    for (int j = (nvec << 2) + tid; j < len; j += NT) {
        float v = logits[base + j];
        float c;
        if (greedy) c = v;
        else        c = fmaf(-t, __logf(fmaxf(noise[base + j], NOISE_MIN)), v);
        if (c > k0 || (c == k0 && j < i0)) { k0 = c; i0 = j; }
    }

    // merge 4 lanes (tie -> min index)
    take_better(k0, i0, k1, i1);
    take_better(k2, i2, k3, i3);
    take_better(k0, i0, k2, i2);

    // warp reduction
    #pragma unroll
    for (int off = 16; off > 0; off >>= 1) {
        float ko = __shfl_down_sync(0xffffffffu, k0, off);
        int   io = __shfl_down_sync(0xffffffffu, i0, off);
        take_better(k0, i0, ko, io);
    }

    // cross-warp
    __shared__ float sk[NT / 32];
    __shared__ int   si[NT / 32];
    const int wid = tid >> 5;
    if (lane == 0) { sk[wid] = k0; si[wid] = i0; }
    __syncthreads();

    if (tid == 0) {
        float bk = sk[0];
        int   bi = si[0];
        #pragma unroll
        for (int w = 1; w < NT / 32; w++) take_better(bk, bi, sk[w], si[w]);
        int gidx = bi + start;  // global vocab index

        // encode: high 32 = ordered key, low 32 = V - idx (max => smallest idx on tie)
        unsigned long long enc =
            ((unsigned long long)ordkey(bk) << 32) |
            (unsigned long long)(unsigned int)(V - gidx);
        atomicMax(&g_slot[row], enc);
        __threadfence();
        unsigned int n = atomicAdd(&g_cnt[row], 1u);
        if (n == (unsigned int)(split - 1)) {
            // last block for this row: all atomicMax for the row are visible
            unsigned long long fin = atomicMax(&g_slot[row], 0ULL);  // coherent read
            int idx = V - (int)(unsigned int)(fin & 0xffffffffULL);
            out[row] = (float)idx;
            // reset scratch for next graph replay (kernel-end flush publishes)
            g_slot[row] = 0ULL;
            g_cnt[row]  = 0u;
        }
    }
}

extern "C" void kernel_launch(void* const* d_in, const int* in_sizes, int n_in,
                              void* d_out, int out_size)
{
    // temps = smallest array; the two largest arrays are {logits, noise}.
    int ti = 0;
    for (int i = 1; i < n_in; i++)
        if (in_sizes[i] < in_sizes[ti]) ti = i;
    int a = -1, b = -1;   // the two largest remaining
    for (int i = 0; i < n_in; i++) {
        if (i == ti) continue;
        if (a < 0 || in_sizes[i] > in_sizes[a]) { b = a; a = i; }
        else if (b < 0 || in_sizes[i] > in_sizes[b]) { b = i; }
    }

    const float* candA = (const float*)d_in[a];
    const float* candB = (const float*)d_in[b];
    const float* temps = (const float*)d_in[ti];
    float*       out   = (float*)d_out;

    const int B = in_sizes[ti];                 // 256
    const int V = in_sizes[a] / B;              // 128000

    int split = SPLIT;
    if (B > MAX_ROWS) split = 1;                // safety; never expected
    int vpart = (V + split - 1) / split;
    vpart = (vpart + 3) & ~3;                   // keep float4 alignment per part

    sampler_fused_kernel<<<B * split, NT>>>(candA, candB, temps, out, V, vpart, split);
}